// round 12
// baseline (speedup 1.0000x reference)
#include <cuda_runtime.h>

// LengthRegulator: out[b,t,:] = x[b, tok(b,t), :] where tok = searchsorted(cumsum(dur), t, 'right')
// Static shapes: B=16, L=512, D=512, T_MAX=4096. Output fp32 [B, T, D].

constexpr int B = 16;
constexpr int L = 512;
constexpr int D = 512;          // 512 floats = 128 float4 per row
constexpr int T = 4096;
constexpr int D4 = D / 4;       // 128 float4 per row

// Scratch token indices: tok[b*T + t], -1 => zero-pad frame. 256 KB device global (no alloc).
__device__ int g_tok[B * T];

// Kernel A: per-batch inclusive scan (shuffle-based) + binary search per output frame.
// grid = B blocks, 512 threads. Critical path: ~2 barriers instead of 18.
__global__ void scan_search_kernel(const int* __restrict__ dur) {
    __shared__ int s[L];          // inclusive cumsum
    __shared__ int wsum[16];      // per-warp totals
    const int b    = blockIdx.x;
    const int tid  = threadIdx.x;
    const int lane = tid & 31;
    const int wrp  = tid >> 5;    // 0..15

    int v = dur[b * L + tid];

    // warp-level inclusive scan
    #pragma unroll
    for (int off = 1; off < 32; off <<= 1) {
        int n = __shfl_up_sync(0xffffffffu, v, off);
        if (lane >= off) v += n;
    }
    if (lane == 31) wsum[wrp] = v;
    __syncthreads();

    // warp 0 scans the 16 partials
    if (wrp == 0 && lane < 16) {
        int p = wsum[lane];
        #pragma unroll
        for (int off = 1; off < 16; off <<= 1) {
            int n = __shfl_up_sync(0x0000ffffu, p, off);
            if (lane >= off) p += n;
        }
        wsum[lane] = p;
    }
    __syncthreads();

    const int base = (wrp > 0) ? wsum[wrp - 1] : 0;
    s[tid] = v + base;
    __syncthreads();

    const int total = s[L - 1];

    // Each thread resolves T/512 = 8 frames via upper_bound binary search in SMEM.
    #pragma unroll
    for (int t = tid; t < T; t += L) {
        int tok;
        if (t >= total) {
            tok = -1;
        } else {
            int lo = 0, hi = L;
            while (lo < hi) {
                int mid = (lo + hi) >> 1;
                if (s[mid] <= t) lo = mid + 1; else hi = mid;
            }
            tok = lo < (L - 1) ? lo : (L - 1);
        }
        g_tok[b * T + t] = tok;
    }
}

// Kernel B (R6 best): one warp per frame, 4 warp-strided float4 per thread,
// fully coalesced LDG/STG.128, warp-uniform tok, streaming stores.
// PDL: blocks launch during kernel A; preamble runs, then grid-dependency sync
// before touching g_tok.
__global__ void gather_kernel(const float4* __restrict__ x4, float4* __restrict__ out4) {
    const int tidg = blockIdx.x * blockDim.x + threadIdx.x;
    const int fr   = tidg >> 5;            // frame index b*T + t  (65536 frames)
    const int lane = tidg & 31;
    const int b    = fr >> 12;             // / T

    const float4* srcb = x4  + (b * L) * D4 + lane;   // preamble: address math
    float4*       dst  = out4 + fr * D4 + lane;

    cudaGridDependencySynchronize();       // wait for scan_search_kernel results

    const int tok = g_tok[fr];             // warp-uniform -> single broadcast load

    if (tok >= 0) {
        const float4* src = srcb + tok * D4;
        float4 v0 = __ldg(src +  0);
        float4 v1 = __ldg(src + 32);
        float4 v2 = __ldg(src + 64);
        float4 v3 = __ldg(src + 96);
        __stcs(dst +  0, v0);
        __stcs(dst + 32, v1);
        __stcs(dst + 64, v2);
        __stcs(dst + 96, v3);
    } else {
        const float4 z = make_float4(0.f, 0.f, 0.f, 0.f);
        __stcs(dst +  0, z);
        __stcs(dst + 32, z);
        __stcs(dst + 64, z);
        __stcs(dst + 96, z);
    }
}

extern "C" void kernel_launch(void* const* d_in, const int* in_sizes, int n_in,
                              void* d_out, int out_size) {
    const float* x   = (const float*)d_in[0];
    const int*   dur = (const int*)d_in[1];
    // d_in[2] = mel_max_length (static 4096, baked into constants)

    scan_search_kernel<<<B, L>>>(dur);

    // Gather with programmatic dependent launch: overlap launch/preamble with kernel A.
    const int total_threads = B * T * 32;      // one warp per frame
    const int threads = 256;

    cudaLaunchConfig_t cfg = {};
    cfg.gridDim  = dim3(total_threads / threads);
    cfg.blockDim = dim3(threads);
    cfg.dynamicSmemBytes = 0;
    cfg.stream = 0;
    cudaLaunchAttribute attrs[1];
    attrs[0].id = cudaLaunchAttributeProgrammaticStreamSerialization;
    attrs[0].val.programmaticStreamSerializationAllowed = 1;
    cfg.attrs = attrs;
    cfg.numAttrs = 1;
    cudaLaunchKernelEx(&cfg, gather_kernel, (const float4*)x, (float4*)d_out);

    (void)in_sizes; (void)n_in; (void)out_size;
}

// round 13
// speedup vs baseline: 1.5393x; 1.5393x over previous
#include <cuda_runtime.h>

// LengthRegulator: out[b,t,:] = x[b, tok(b,t), :] where tok = searchsorted(cumsum(dur), t, 'right')
// Static shapes: B=16, L=512, D=512, T_MAX=4096. Output fp32 [B, T, D].
//
// FUSED single kernel: each block (8 warps = 8 consecutive frames of one batch)
// redundantly scans that batch's 512 durations (2KB, L2-hit), binary-searches the
// token per warp, then does the R6-style fully-coalesced warp gather.

constexpr int B = 16;
constexpr int L = 512;
constexpr int D = 512;          // 512 floats = 128 float4 per row
constexpr int T = 4096;
constexpr int D4 = D / 4;       // 128 float4 per row

__global__ void __launch_bounds__(256) fused_kernel(
    const int*    __restrict__ dur,
    const float4* __restrict__ x4,
    float4*       __restrict__ out4)
{
    __shared__ int s[L];         // inclusive cumsum of durations for this batch
    __shared__ int wsum[8];      // per-warp pair-scan totals

    const int tid  = threadIdx.x;        // 0..255
    const int lane = tid & 31;
    const int wrp  = tid >> 5;           // 0..7
    const int fr0  = blockIdx.x << 3;    // first of 8 consecutive frames
    const int b    = fr0 >> 12;          // batch (uniform per block: 512 blocks/batch)

    // ---- redundant per-block scan of dur[b, 0..511] (2 ints per thread) ----
    const int d0 = dur[b * L + 2 * tid];
    const int d1 = dur[b * L + 2 * tid + 1];
    int v = d0 + d1;

    #pragma unroll
    for (int off = 1; off < 32; off <<= 1) {       // warp inclusive scan of pair sums
        int n = __shfl_up_sync(0xffffffffu, v, off);
        if (lane >= off) v += n;
    }
    if (lane == 31) wsum[wrp] = v;
    __syncthreads();

    if (wrp == 0 && lane < 8) {                    // scan the 8 warp totals
        int p = wsum[lane];
        #pragma unroll
        for (int off = 1; off < 8; off <<= 1) {
            int n = __shfl_up_sync(0x000000ffu, p, off);
            if (lane >= off) p += n;
        }
        wsum[lane] = p;
    }
    __syncthreads();

    const int base = (wrp > 0) ? wsum[wrp - 1] : 0;
    const int incl = v + base;                     // inclusive cumsum at element 2*tid+1
    s[2 * tid]     = incl - d1;
    s[2 * tid + 1] = incl;
    __syncthreads();

    const int total = s[L - 1];

    // ---- per-warp token: upper_bound search in SMEM (all lanes uniform, broadcast) ----
    const int fr = fr0 + wrp;
    const int t  = fr & (T - 1);
    int tok;
    if (t >= total) {
        tok = -1;
    } else {
        int lo = 0, hi = L;
        while (lo < hi) {
            int mid = (lo + hi) >> 1;
            if (s[mid] <= t) lo = mid + 1; else hi = mid;
        }
        tok = lo < (L - 1) ? lo : (L - 1);
    }

    // ---- gather: 4 warp-strided float4 per thread, fully coalesced ----
    float4* dst = out4 + fr * D4 + lane;
    if (tok >= 0) {
        const float4* src = x4 + (b * L + tok) * D4 + lane;
        float4 v0 = __ldg(src +  0);
        float4 v1 = __ldg(src + 32);
        float4 v2 = __ldg(src + 64);
        float4 v3 = __ldg(src + 96);
        __stcs(dst +  0, v0);
        __stcs(dst + 32, v1);
        __stcs(dst + 64, v2);
        __stcs(dst + 96, v3);
    } else {
        const float4 z = make_float4(0.f, 0.f, 0.f, 0.f);
        __stcs(dst +  0, z);
        __stcs(dst + 32, z);
        __stcs(dst + 64, z);
        __stcs(dst + 96, z);
    }
}

extern "C" void kernel_launch(void* const* d_in, const int* in_sizes, int n_in,
                              void* d_out, int out_size) {
    const float* x   = (const float*)d_in[0];
    const int*   dur = (const int*)d_in[1];
    // d_in[2] = mel_max_length (static 4096, baked into constants)

    const int blocks = (B * T) / 8;     // 8192 blocks, 8 frames each
    fused_kernel<<<blocks, 256>>>(dur, (const float4*)x, (float4*)d_out);

    (void)in_sizes; (void)n_in; (void)out_size;
}